// round 11
// baseline (speedup 1.0000x reference)
#include <cuda_runtime.h>
#include <cuda_bf16.h>
#include <cstdint>
#include <stdint.h>
#include <math.h>

#define H      1024
#define FF     4096
#define E      8
#define T_MAX  8192
#define NROWS  (T_MAX * 2)
#define NROWSP 20480          // padded rows (per-expert base aligned to 512)
#define KC     32             // K-chunk
#define TB     8192           // one tile: 128 rows x 64 bytes (SW64), contiguous in global
#define NKC_H  (H / KC)       // 32
#define NKC_F  (FF / KC)      // 128
#define NST    4              // pipeline stages

#if defined(__CUDA_ARCH_FEAT_SM103_ALL) || defined(__CUDA_ARCH_FEAT_SM100_ALL)
#define TC_OK 1
#else
#define TC_OK 0
#endif

// ---------------- device scratch ----------------
__device__ int   g_counts[E];
__device__ int   g_base[E];
__device__ int   g_pbase[E];   // padded-to-512 cumulative
__device__ int   g_list[E * T_MAX];
__device__ float g_wts[T_MAX * 2];
__device__ __nv_bfloat16 g_ax_hi[(size_t)NROWSP * H];
__device__ __nv_bfloat16 g_ax_lo[(size_t)NROWSP * H];
__device__ __nv_bfloat16 g_w1h[(size_t)E * FF * H];
__device__ __nv_bfloat16 g_w1l[(size_t)E * FF * H];
__device__ __nv_bfloat16 g_w3h[(size_t)E * FF * H];
__device__ __nv_bfloat16 g_w3l[(size_t)E * FF * H];
__device__ __nv_bfloat16 g_w2h[(size_t)E * H * FF];
__device__ __nv_bfloat16 g_w2l[(size_t)E * H * FF];
__device__ __nv_bfloat16 g_act_hi[(size_t)NROWSP * FF];
__device__ __nv_bfloat16 g_act_lo[(size_t)NROWSP * FF];
__device__ float g_ybuf[(size_t)NROWS * H];

// ---------------- PTX helpers ----------------
__device__ __forceinline__ uint32_t smem_u32(const void* p) {
    uint32_t a;
    asm("{ .reg .u64 t; cvta.to.shared.u64 t, %1; cvt.u32.u64 %0, t; }" : "=r"(a) : "l"(p));
    return a;
}
__device__ __forceinline__ uint32_t cta_rank() {
    uint32_t r; asm("mov.u32 %0, %%cluster_ctarank;" : "=r"(r)); return r;
}
#define MBAR_INIT(a, c) asm volatile("mbarrier.init.shared.b64 [%0], %1;" :: "r"((uint32_t)(a)), "r"((uint32_t)(c)) : "memory")
#define MBAR_EXPECT(a, n) asm volatile("mbarrier.arrive.expect_tx.shared.b64 _, [%0], %1;" :: "r"((uint32_t)(a)), "r"((uint32_t)(n)) : "memory")
#define ARRIVE_REMOTE0(local) asm volatile("{\n\t.reg .b32 r;\n\tmapa.shared::cluster.u32 r, %0, 0;\n\tmbarrier.arrive.shared::cluster.b64 _, [r];\n\t}" :: "r"((uint32_t)(local)) : "memory")
#define CLUSTER_SYNC() do { \
    asm volatile("barrier.cluster.arrive.aligned;" ::: "memory"); \
    asm volatile("barrier.cluster.wait.aligned;" ::: "memory"); \
} while (0)
#define MBAR_WAIT(a, ph) do { \
    uint32_t _m = (uint32_t)(a), _p = (uint32_t)(ph), _d; \
    asm volatile("{\n\t.reg .pred p;\n\tmbarrier.try_wait.parity.acquire.cta.shared::cta.b64 p, [%1], %2;\n\tselp.b32 %0,1,0,p;\n\t}" \
        : "=r"(_d) : "r"(_m), "r"(_p) : "memory"); \
    if (!_d) { asm volatile("{\n\t.reg .pred P1;\n\tWL_%=:\n\t" \
        "mbarrier.try_wait.parity.acquire.cta.shared::cta.b64 P1, [%0], %1, 0x989680;\n\t" \
        "@P1 bra.uni WD_%=;\n\tbra.uni WL_%=;\n\tWD_%=:\n\t}" :: "r"(_m), "r"(_p) : "memory"); } \
} while (0)

#if TC_OK
#define BULK(d, s, mb) asm volatile( \
    "cp.async.bulk.shared::cta.global.mbarrier::complete_tx::bytes [%0], [%1], %2, [%3];" \
    :: "r"((uint32_t)(d)), "l"(s), "r"(8192u), "r"((uint32_t)(mb)) : "memory")
#define TC_ALLOC_CG2(sa, n)   asm volatile("tcgen05.alloc.cta_group::2.sync.aligned.shared::cta.b32 [%0], %1;" :: "r"((uint32_t)(sa)), "r"((uint32_t)(n)) : "memory")
#define TC_DEALLOC_CG2(tm, n) asm volatile("tcgen05.dealloc.cta_group::2.sync.aligned.b32 %0, %1;" :: "r"(tm), "r"((uint32_t)(n)))
#define TC_RELINQ_CG2()       asm volatile("tcgen05.relinquish_alloc_permit.cta_group::2.sync.aligned;")
#define TC_COMMIT_MC2(mb, mask) asm volatile( \
    "tcgen05.commit.cta_group::2.mbarrier::arrive::one.shared::cluster.multicast::cluster.b64 [%0], %1;" \
    :: "r"((uint32_t)(mb)), "h"((uint16_t)(mask)) : "memory")
#define TC_FENCE_AFTER()  asm volatile("tcgen05.fence::after_thread_sync;" ::: "memory")
#define TC_FENCE_BEFORE() asm volatile("tcgen05.fence::before_thread_sync;" ::: "memory")
#define TC_WAIT_LD()      asm volatile("tcgen05.wait::ld.sync.aligned;" ::: "memory")
#define TC_LD_X32(r, ta) \
    asm volatile("tcgen05.ld.sync.aligned.32x32b.x32.b32 " \
        "{%0,%1,%2,%3,%4,%5,%6,%7,%8,%9,%10,%11,%12,%13,%14,%15," \
        "%16,%17,%18,%19,%20,%21,%22,%23,%24,%25,%26,%27,%28,%29,%30,%31}, [%32];" \
        : "=r"((r)[0]), "=r"((r)[1]), "=r"((r)[2]), "=r"((r)[3]), "=r"((r)[4]), "=r"((r)[5]), "=r"((r)[6]), "=r"((r)[7]), \
          "=r"((r)[8]), "=r"((r)[9]), "=r"((r)[10]), "=r"((r)[11]), "=r"((r)[12]), "=r"((r)[13]), "=r"((r)[14]), "=r"((r)[15]), \
          "=r"((r)[16]), "=r"((r)[17]), "=r"((r)[18]), "=r"((r)[19]), "=r"((r)[20]), "=r"((r)[21]), "=r"((r)[22]), "=r"((r)[23]), \
          "=r"((r)[24]), "=r"((r)[25]), "=r"((r)[26]), "=r"((r)[27]), "=r"((r)[28]), "=r"((r)[29]), "=r"((r)[30]), "=r"((r)[31]) \
        : "r"(ta))

// SW64 K-major descriptor: layout=4, version=1, SBO=32, LBO=1
static constexpr uint64_t DESC_SW64 =
    (uint64_t(4) << 61) | (uint64_t(1) << 46) | (uint64_t(32) << 32) | (uint64_t(1) << 16);
#define MK_DESC(a) (DESC_SW64 | ((uint64_t)((a) >> 4) & 0x3FFF))
// idesc kind::f16 cg2: F32 out, BF16 a/b, M=256 (16<<24), N=256 (32<<17)
#define IDESC_CG2 ((1u << 4) | (1u << 7) | (1u << 10) | (32u << 17) | (16u << 24))

__device__ __forceinline__ void mma_cg2(uint32_t d, uint64_t a, uint64_t b, uint32_t en) {
    asm volatile("{\n\t.reg .pred p;\n\tsetp.ne.u32 p, %4, 0;\n\t"
        "tcgen05.mma.cta_group::2.kind::f16 [%0], %1, %2, %3, {%5,%5,%5,%5,%5,%5,%5,%5}, p;\n\t}"
        :: "r"(d), "l"(a), "l"(b), "r"(IDESC_CG2), "r"(en), "r"(0u) : "memory");
}
#endif  // TC_OK

__device__ __forceinline__ uint32_t pack_hi(float a, float b, uint32_t& lo) {
    __nv_bfloat16 h0 = __float2bfloat16(a), h1 = __float2bfloat16(b);
    __nv_bfloat16 l0 = __float2bfloat16(a - __bfloat162float(h0));
    __nv_bfloat16 l1 = __float2bfloat16(b - __bfloat162float(h1));
    lo = (uint32_t)__bfloat16_as_ushort(l0) | ((uint32_t)__bfloat16_as_ushort(l1) << 16);
    return (uint32_t)__bfloat16_as_ushort(h0) | ((uint32_t)__bfloat16_as_ushort(h1) << 16);
}

// ---------------- routing ----------------
__global__ void k_zero() { if (threadIdx.x < E) g_counts[threadIdx.x] = 0; }

__global__ void k_router(const float* __restrict__ x, const float* __restrict__ gate,
                         float* __restrict__ logits_out, int T) {
    __shared__ float sg[E * H];
    for (int i = threadIdx.x; i < E * H; i += blockDim.x) sg[i] = gate[i];
    __syncthreads();
    int warp = threadIdx.x >> 5, lane = threadIdx.x & 31;
    int t = blockIdx.x * 8 + warp;
    if (t >= T) return;
    const float* xr = x + (size_t)t * H;
    float acc[E];
#pragma unroll
    for (int e = 0; e < E; e++) acc[e] = 0.f;
    for (int k = lane; k < H; k += 32) {
        float xv = xr[k];
#pragma unroll
        for (int e = 0; e < E; e++) acc[e] += xv * sg[e * H + k];
    }
#pragma unroll
    for (int e = 0; e < E; e++)
#pragma unroll
        for (int o = 16; o > 0; o >>= 1) acc[e] += __shfl_down_sync(0xffffffffu, acc[e], o);
    if (lane == 0) {
#pragma unroll
        for (int e = 0; e < E; e++) logits_out[(size_t)t * E + e] = acc[e];
        int e0 = 0; float l0 = acc[0];
#pragma unroll
        for (int e = 1; e < E; e++) if (acc[e] > l0) { l0 = acc[e]; e0 = e; }
        int e1 = -1; float l1 = -1e30f;
#pragma unroll
        for (int e = 0; e < E; e++) if (e != e0 && acc[e] > l1) { l1 = acc[e]; e1 = e; }
        float s = 0.f, pe[E];
#pragma unroll
        for (int e = 0; e < E; e++) { pe[e] = expf(acc[e] - l0); s += pe[e]; }
        float p0 = pe[e0] / s, p1 = pe[e1] / s;
        float inv = 1.f / (p0 + p1);
        int q0 = atomicAdd(&g_counts[e0], 1);
        g_list[e0 * T_MAX + q0] = (t << 1);
        g_wts[(t << 1)] = p0 * inv;
        int q1 = atomicAdd(&g_counts[e1], 1);
        g_list[e1 * T_MAX + q1] = (t << 1) | 1;
        g_wts[(t << 1) | 1] = p1 * inv;
    }
}

__global__ void k_base() {
    if (threadIdx.x == 0) {
        int s = 0, ps = 0;
#pragma unroll
        for (int e = 0; e < E; e++) {
            g_base[e] = s;  g_pbase[e] = ps;
            s += g_counts[e];
            ps += (g_counts[e] + 511) & ~511;
        }
    }
}

// fp32 -> bf16 hi/lo, pre-tiled + pre-swizzled
__global__ void k_split8(const float* __restrict__ src, __nv_bfloat16* __restrict__ hi,
                         __nv_bfloat16* __restrict__ lo, long n8, int K, int nkc) {
    long i = (long)blockIdx.x * blockDim.x + threadIdx.x;
    if (i >= n8) return;
    long f = i * 8;
    int row = (int)(f / K), k0 = (int)(f % K);
    int kc = k0 >> 5, c = (k0 & 31) >> 3;
    int rr = row & 127, tr = row >> 7;
    size_t off = ((size_t)tr * nkc + kc) * TB + (size_t)rr * 64 + ((c ^ ((rr >> 1) & 3)) << 4);
    const float4* s4 = (const float4*)(src + f);
    float4 a = s4[0], b = s4[1];
    float v[8] = {a.x, a.y, a.z, a.w, b.x, b.y, b.z, b.w};
    uint32_t ph[4], pl[4];
#pragma unroll
    for (int j = 0; j < 4; j++) ph[j] = pack_hi(v[2 * j], v[2 * j + 1], pl[j]);
    *(uint4*)((char*)hi + off) = make_uint4(ph[0], ph[1], ph[2], ph[3]);
    *(uint4*)((char*)lo + off) = make_uint4(pl[0], pl[1], pl[2], pl[3]);
}

// gather x rows into expert-grouped (padded) tiled hi/lo
__global__ void k_gather(const float* __restrict__ x, int total) {
    int g = blockIdx.x;
    if (g >= total) return;
    int e = 0;
#pragma unroll
    for (int k = 1; k < E; k++) if (g >= g_base[k]) e = k;
    int pos = g - g_base[e];
    int tok = g_list[e * T_MAX + pos] >> 1;
    int prow = g_pbase[e] + pos;
    int rr = prow & 127, tr = prow >> 7;
    int tid = threadIdx.x;                 // 0..127
    int kc = tid >> 2, c = tid & 3;
    size_t off = ((size_t)tr * NKC_H + kc) * TB + (size_t)rr * 64 + ((c ^ ((rr >> 1) & 3)) << 4);
    const float4* src = (const float4*)(x + (size_t)tok * H + tid * 8);
    float4 a = src[0], b = src[1];
    float v[8] = {a.x, a.y, a.z, a.w, b.x, b.y, b.z, b.w};
    uint32_t ph[4], pl[4];
#pragma unroll
    for (int j = 0; j < 4; j++) ph[j] = pack_hi(v[2 * j], v[2 * j + 1], pl[j]);
    *(uint4*)((char*)g_ax_hi + off) = make_uint4(ph[0], ph[1], ph[2], ph[3]);
    *(uint4*)((char*)g_ax_lo + off) = make_uint4(pl[0], pl[1], pl[2], pl[3]);
}

#define SM_T 1024

#if TC_OK
// one stage fill (6 tiles, 48KB) -> local full barrier
__device__ __forceinline__ void bulk6(uint32_t sb, int buf,
    const __nv_bfloat16* Ah, const __nv_bfloat16* Al, int trA, int nkcA,
    const __nv_bfloat16* Wh, const __nv_bfloat16* Wl, int trW, int nkcW, int kc) {
    uint32_t mb = sb + 8 + buf * 8;
    uint32_t dst = sb + SM_T + buf * 6 * TB;
    size_t a0 = ((size_t)trA * nkcA + kc) * TB;
    size_t a1 = ((size_t)(trA + 1) * nkcA + kc) * TB;
    size_t w  = ((size_t)trW * nkcW + kc) * TB;
    BULK(dst + 0 * TB, (const char*)Ah + a0, mb);
    BULK(dst + 1 * TB, (const char*)Al + a0, mb);
    BULK(dst + 2 * TB, (const char*)Ah + a1, mb);
    BULK(dst + 3 * TB, (const char*)Al + a1, mb);
    BULK(dst + 4 * TB, (const char*)Wh + w, mb);
    BULK(dst + 5 * TB, (const char*)Wl + w, mb);
}

// tid0-only cg2 pipeline (4 stages): leader (rank0) MMAs + multicast commits; follower arrives remotely
__device__ void run_pipeline(uint32_t sb, uint32_t tm, int NCH, int rank,
    const __nv_bfloat16* Ah, const __nv_bfloat16* Al, int trA, int nkcA,
    const __nv_bfloat16* Wh, const __nv_bfloat16* Wl, int trW, int nkcW) {
    bulk6(sb, 0, Ah, Al, trA, nkcA, Wh, Wl, trW, nkcW, 0);
    bulk6(sb, 1, Ah, Al, trA, nkcA, Wh, Wl, trW, nkcW, 1);
    bulk6(sb, 2, Ah, Al, trA, nkcA, Wh, Wl, trW, nkcW, 2);
    for (int i = 0; i < NCH; i++) {
        int b = i & (NST - 1);
        MBAR_WAIT(sb + 8 + b * 8, (i >> 2) & 1);
        MBAR_EXPECT(sb + 8 + b * 8, 6 * TB);          // re-arm next phase
        if (rank == 0) {
            uint32_t tb = sb + SM_T + b * 6 * TB;
            uint64_t dA0h = MK_DESC(tb),          dA0l = MK_DESC(tb + TB);
            uint64_t dA1h = MK_DESC(tb + 2 * TB), dA1l = MK_DESC(tb + 3 * TB);
            uint64_t dWh  = MK_DESC(tb + 4 * TB), dWl  = MK_DESC(tb + 5 * TB);
#pragma unroll
            for (int ks = 0; ks < 2; ks++) {
                uint64_t o = (uint64_t)(2 * ks);
                uint32_t en = (i > 0 || ks > 0) ? 1u : 0u;
                mma_cg2(tm,       dA0h + o, dWh + o, en);
                mma_cg2(tm,       dA0h + o, dWl + o, 1);
                mma_cg2(tm,       dA0l + o, dWh + o, 1);
                mma_cg2(tm + 256, dA1h + o, dWh + o, en);
                mma_cg2(tm + 256, dA1h + o, dWl + o, 1);
                mma_cg2(tm + 256, dA1l + o, dWh + o, 1);
            }
            TC_COMMIT_MC2(sb + 48 + b * 8, 0x3);
        } else {
            ARRIVE_REMOTE0(sb + 8 + b * 8);
        }
        if (i + 3 < NCH) {
            int nb = (i + 3) & (NST - 1);   // == (i-1)&3: reuse chunk i-1's buffer
            if (i >= 1) MBAR_WAIT(sb + 48 + nb * 8, ((i - 1) >> 2) & 1);
            bulk6(sb, nb, Ah, Al, trA, nkcA, Wh, Wl, trW, nkcW, i + 3);
        }
    }
    for (int c = NCH - NST; c < NCH; c++)
        MBAR_WAIT(sb + 48 + (c & (NST - 1)) * 8, (c >> 2) & 1);
}
#endif

// ---------------- cg2 GEMM13: pair BM=512, BN=128 ([D1|D3]=256 cols) ----------------
// cluster (2,1,1): pair id = blockIdx.x>>1, rank = ctarank
__global__ __launch_bounds__(256, 1) __cluster_dims__(2, 1, 1) void k_mma13() {
#if TC_OK
    int e = blockIdx.z;
    int cnt = g_counts[e];
    int row0 = (blockIdx.x >> 1) * 512;
    if (row0 >= cnt) return;
    int rank = (int)cta_rank();
    int n0 = blockIdx.y * 128;
    int rbase = g_pbase[e] + row0 + rank * 256;
    int trA = rbase >> 7;
    int trW = (e * FF + n0) >> 7;
    const __nv_bfloat16* Wh = rank ? g_w3h : g_w1h;
    const __nv_bfloat16* Wl = rank ? g_w3l : g_w1l;

    extern __shared__ char sm[];
    uint32_t sb = smem_u32(sm);
    int tid = threadIdx.x, wid = tid >> 5, lid = tid & 31;

    if (wid == 0) TC_ALLOC_CG2(sb, 512);
    if (tid == 0) {
#pragma unroll
        for (int b = 0; b < NST; b++) {
            MBAR_INIT(sb + 8 + b * 8, rank == 0 ? 2 : 1);   // full: leader expect + follower arrive
            MBAR_INIT(sb + 48 + b * 8, 1);                   // mmadone (multicast commit)
            MBAR_EXPECT(sb + 8 + b * 8, 6 * TB);
        }
    }
    __syncthreads();
    CLUSTER_SYNC();
    uint32_t tm;
    asm volatile("ld.shared.b32 %0, [%1];" : "=r"(tm) : "r"(sb));

    if (tid == 0)
        run_pipeline(sb, tm, NKC_H, rank, g_ax_hi, g_ax_lo, trA, NKC_H, Wh, Wl, trW, NKC_H);
    __syncthreads();
    TC_FENCE_AFTER();

    // epilogue: 8 warps = 2 accumulators x 4 subpartitions; local rows = a*128+sub*32+lid
    int a = wid >> 2, sub = wid & 3;
    int lrow = a * 128 + sub * 32 + lid;
    bool valid = (row0 + rank * 256 + lrow) < cnt;
    int prow = rbase + lrow;
    int rr = prow & 127, tr = prow >> 7, sw = (rr >> 1) & 3;
#pragma unroll
    for (int c0 = 0; c0 < 128; c0 += 32) {
        uint32_t d1[32], d3[32];
        TC_LD_X32(d1, tm + a * 256 + c0);
        TC_LD_X32(d3, tm + a * 256 + 128 + c0);
        TC_WAIT_LD();
        if (valid) {
            uint32_t ph[16], pl[16];
#pragma unroll
            for (int j = 0; j < 16; j++) {
                float h0 = __uint_as_float(d1[2 * j]),     v0 = __uint_as_float(d3[2 * j]);
                float h1 = __uint_as_float(d1[2 * j + 1]), v1 = __uint_as_float(d3[2 * j + 1]);
                float a0 = (h0 / (1.f + __expf(-h0))) * v0;
                float a1 = (h1 / (1.f + __expf(-h1))) * v1;
                ph[j] = pack_hi(a0, a1, pl[j]);
            }
            int kc = (n0 >> 5) + (c0 >> 5);
            size_t tbo = ((size_t)tr * NKC_F + kc) * TB + (size_t)rr * 64;
#pragma unroll
            for (int q = 0; q < 4; q++) {
                size_t o = tbo + ((q ^ sw) << 4);
                *(uint4*)((char*)g_act_hi + o) = make_uint4(ph[4 * q], ph[4 * q + 1], ph[4 * q + 2], ph[4 * q + 3]);
                *(uint4*)((char*)g_act_lo + o) = make_uint4(pl[4 * q], pl[4 * q + 1], pl[4 * q + 2], pl[4 * q + 3]);
            }
        }
    }
    TC_FENCE_BEFORE();
    __syncthreads();
    if (wid == 0) { TC_RELINQ_CG2(); TC_DEALLOC_CG2(tm, 512); }
    CLUSTER_SYNC();
#endif
}

// ---------------- cg2 GEMM2: pair BM=512, BN=256 ----------------
__global__ __launch_bounds__(256, 1) __cluster_dims__(2, 1, 1) void k_mma2() {
#if TC_OK
    int e = blockIdx.z;
    int cnt = g_counts[e];
    int row0 = (blockIdx.x >> 1) * 512;
    if (row0 >= cnt) return;
    int rank = (int)cta_rank();
    int n0 = blockIdx.y * 256;
    int rbase = g_pbase[e] + row0 + rank * 256;
    int trA = rbase >> 7;
    int trW = (e * H + n0 + rank * 128) >> 7;   // each CTA loads its half of B rows

    extern __shared__ char sm[];
    uint32_t sb = smem_u32(sm);
    int tid = threadIdx.x, wid = tid >> 5, lid = tid & 31;

    if (wid == 0) TC_ALLOC_CG2(sb, 512);
    if (tid == 0) {
#pragma unroll
        for (int b = 0; b < NST; b++) {
            MBAR_INIT(sb + 8 + b * 8, rank == 0 ? 2 : 1);
            MBAR_INIT(sb + 48 + b * 8, 1);
            MBAR_EXPECT(sb + 8 + b * 8, 6 * TB);
        }
    }
    __syncthreads();
    CLUSTER_SYNC();
    uint32_t tm;
    asm volatile("ld.shared.b32 %0, [%1];" : "=r"(tm) : "r"(sb));

    if (tid == 0)
        run_pipeline(sb, tm, NKC_F, rank, g_act_hi, g_act_lo, trA, NKC_F, g_w2h, g_w2l, trW, NKC_F);
    __syncthreads();
    TC_FENCE_AFTER();

    int a = wid >> 2, sub = wid & 3;
    int lrow = a * 128 + sub * 32 + lid;
    bool valid = (row0 + rank * 256 + lrow) < cnt;
    int ts = 0; float w = 0.f;
    if (valid) { ts = g_list[e * T_MAX + row0 + rank * 256 + lrow]; w = g_wts[ts]; }
    float* yrow = g_ybuf + (size_t)ts * H + n0;
#pragma unroll
    for (int c0 = 0; c0 < 256; c0 += 32) {
        uint32_t d[32];
        TC_LD_X32(d, tm + a * 256 + c0);
        TC_WAIT_LD();
        if (valid) {
            float4* dst = (float4*)(yrow + c0);
#pragma unroll
            for (int q = 0; q < 8; q++)
                dst[q] = make_float4(w * __uint_as_float(d[4 * q]), w * __uint_as_float(d[4 * q + 1]),
                                     w * __uint_as_float(d[4 * q + 2]), w * __uint_as_float(d[4 * q + 3]));
        }
    }
    TC_FENCE_BEFORE();
    __syncthreads();
    if (wid == 0) { TC_RELINQ_CG2(); TC_DEALLOC_CG2(tm, 512); }
    CLUSTER_SYNC();
#endif
}

__global__ void k_combine(float* __restrict__ out, int T) {
    int i = blockIdx.x * blockDim.x + threadIdx.x;
    int total = T * (H / 4);
    if (i >= total) return;
    int t = i / (H / 4);
    int h4 = i - t * (H / 4);
    const float4* yb = (const float4*)g_ybuf;
    float4 a = yb[(size_t)(2 * t) * (H / 4) + h4];
    float4 b = yb[(size_t)(2 * t + 1) * (H / 4) + h4];
    ((float4*)out)[i] = make_float4(a.x + b.x, a.y + b.y, a.z + b.z, a.w + b.w);
}

// ---------------- launch ----------------
extern "C" void kernel_launch(void* const* d_in, const int* in_sizes, int n_in,
                              void* d_out, int out_size) {
    const float* x;
    const float* gate;
    if (in_sizes[0] > in_sizes[1]) { x = (const float*)d_in[0]; gate = (const float*)d_in[1]; }
    else                           { gate = (const float*)d_in[0]; x = (const float*)d_in[1]; }
    const float* w1 = (const float*)d_in[2];
    const float* w2 = (const float*)d_in[3];
    const float* w3 = (const float*)d_in[4];
    int T = (in_sizes[0] > in_sizes[1] ? in_sizes[0] : in_sizes[1]) / H;

    float* out = (float*)d_out;
    float* logits_out = out + (size_t)T * H;

    int smem = SM_T + NST * 6 * TB;  // 197,632
    cudaFuncSetAttribute(k_mma13, cudaFuncAttributeMaxDynamicSharedMemorySize, smem);
    cudaFuncSetAttribute(k_mma2,  cudaFuncAttributeMaxDynamicSharedMemorySize, smem);

    __nv_bfloat16 *w1h, *w1l, *w3h, *w3l, *w2h, *w2l;
    cudaGetSymbolAddress((void**)&w1h, g_w1h); cudaGetSymbolAddress((void**)&w1l, g_w1l);
    cudaGetSymbolAddress((void**)&w3h, g_w3h); cudaGetSymbolAddress((void**)&w3l, g_w3l);
    cudaGetSymbolAddress((void**)&w2h, g_w2h); cudaGetSymbolAddress((void**)&w2l, g_w2l);

    k_zero<<<1, 32>>>();
    k_router<<<(T + 7) / 8, 256>>>(x, gate, logits_out, T);
    k_base<<<1, 1>>>();

    long n8 = (long)E * FF * H / 8;
    int sblk = (int)((n8 + 255) / 256);
    k_split8<<<sblk, 256>>>(w1, w1h, w1l, n8, H, NKC_H);
    k_split8<<<sblk, 256>>>(w3, w3h, w3l, n8, H, NKC_H);
    k_split8<<<sblk, 256>>>(w2, w2h, w2l, n8, FF, NKC_F);
    k_gather<<<2 * T, 128>>>(x, 2 * T);

    // cg2 launches: cluster (2,1,1) via cudaLaunchKernelEx
    cudaLaunchAttribute attrs[1];
    attrs[0].id = cudaLaunchAttributeClusterDimension;
    attrs[0].val.clusterDim.x = 2; attrs[0].val.clusterDim.y = 1; attrs[0].val.clusterDim.z = 1;

    cudaLaunchConfig_t cfg13 = {};
    cfg13.gridDim  = dim3(32, FF / 128, E);   // x: 16 pairs (worst-case cnt=8192), early exit
    cfg13.blockDim = dim3(256, 1, 1);
    cfg13.dynamicSmemBytes = smem;
    cfg13.attrs = attrs; cfg13.numAttrs = 1;
    cudaLaunchKernelEx(&cfg13, k_mma13);

    cudaLaunchConfig_t cfg2 = {};
    cfg2.gridDim  = dim3(32, H / 256, E);
    cfg2.blockDim = dim3(256, 1, 1);
    cfg2.dynamicSmemBytes = smem;
    cfg2.attrs = attrs; cfg2.numAttrs = 1;
    cudaLaunchKernelEx(&cfg2, k_mma2);

    k_combine<<<(T * (H / 4) + 255) / 256, 256>>>(out, T);
}

// round 12
// speedup vs baseline: 1.0434x; 1.0434x over previous
#include <cuda_runtime.h>
#include <cuda_bf16.h>
#include <cstdint>
#include <stdint.h>
#include <math.h>

#define H      1024
#define FF     4096
#define E      8
#define T_MAX  8192
#define NROWS  (T_MAX * 2)
#define NROWSP 20480          // padded rows (per-expert base aligned to 512)
#define KC     32             // K-chunk
#define TB     8192           // one tile: 128 rows x 64 bytes (SW64), contiguous in global
#define NKC_H  (H / KC)       // 32  (== 0 mod 8: parity-safe across jobs)
#define NKC_F  (FF / KC)      // 128 (== 0 mod 8)
#define NST    4              // pipeline stages
#define NCTA   148            // persistent CTAs (74 cg2 pairs)

#if defined(__CUDA_ARCH_FEAT_SM103_ALL) || defined(__CUDA_ARCH_FEAT_SM100_ALL)
#define TC_OK 1
#else
#define TC_OK 0
#endif

// ---------------- device scratch ----------------
__device__ int   g_counts[E];
__device__ int   g_base[E];
__device__ int   g_pbase[E];   // padded-to-512 cumulative
__device__ int   g_jb13[E];    // job base (gemm13): prefix of ceil(cnt/512)*32
__device__ int   g_J13;
__device__ int   g_jb2[E];     // job base (gemm2): prefix of ceil(cnt/512)*4
__device__ int   g_J2;
__device__ int   g_list[E * T_MAX];
__device__ float g_wts[T_MAX * 2];
__device__ __nv_bfloat16 g_ax_hi[(size_t)NROWSP * H];
__device__ __nv_bfloat16 g_ax_lo[(size_t)NROWSP * H];
__device__ __nv_bfloat16 g_w1h[(size_t)E * FF * H];
__device__ __nv_bfloat16 g_w1l[(size_t)E * FF * H];
__device__ __nv_bfloat16 g_w3h[(size_t)E * FF * H];
__device__ __nv_bfloat16 g_w3l[(size_t)E * FF * H];
__device__ __nv_bfloat16 g_w2h[(size_t)E * H * FF];
__device__ __nv_bfloat16 g_w2l[(size_t)E * H * FF];
__device__ __nv_bfloat16 g_act_hi[(size_t)NROWSP * FF];
__device__ __nv_bfloat16 g_act_lo[(size_t)NROWSP * FF];
__device__ float g_ybuf[(size_t)NROWS * H];

// ---------------- PTX helpers ----------------
__device__ __forceinline__ uint32_t smem_u32(const void* p) {
    uint32_t a;
    asm("{ .reg .u64 t; cvta.to.shared.u64 t, %1; cvt.u32.u64 %0, t; }" : "=r"(a) : "l"(p));
    return a;
}
__device__ __forceinline__ uint32_t cta_rank() {
    uint32_t r; asm("mov.u32 %0, %%cluster_ctarank;" : "=r"(r)); return r;
}
#define MBAR_INIT(a, c) asm volatile("mbarrier.init.shared.b64 [%0], %1;" :: "r"((uint32_t)(a)), "r"((uint32_t)(c)) : "memory")
#define MBAR_EXPECT(a, n) asm volatile("mbarrier.arrive.expect_tx.shared.b64 _, [%0], %1;" :: "r"((uint32_t)(a)), "r"((uint32_t)(n)) : "memory")
#define ARRIVE_REMOTE0(local) asm volatile("{\n\t.reg .b32 r;\n\tmapa.shared::cluster.u32 r, %0, 0;\n\tmbarrier.arrive.shared::cluster.b64 _, [r];\n\t}" :: "r"((uint32_t)(local)) : "memory")
#define CLUSTER_SYNC() do { \
    asm volatile("barrier.cluster.arrive.aligned;" ::: "memory"); \
    asm volatile("barrier.cluster.wait.aligned;" ::: "memory"); \
} while (0)
#define MBAR_WAIT(a, ph) do { \
    uint32_t _m = (uint32_t)(a), _p = (uint32_t)(ph), _d; \
    asm volatile("{\n\t.reg .pred p;\n\tmbarrier.try_wait.parity.acquire.cta.shared::cta.b64 p, [%1], %2;\n\tselp.b32 %0,1,0,p;\n\t}" \
        : "=r"(_d) : "r"(_m), "r"(_p) : "memory"); \
    if (!_d) { asm volatile("{\n\t.reg .pred P1;\n\tWL_%=:\n\t" \
        "mbarrier.try_wait.parity.acquire.cta.shared::cta.b64 P1, [%0], %1, 0x989680;\n\t" \
        "@P1 bra.uni WD_%=;\n\tbra.uni WL_%=;\n\tWD_%=:\n\t}" :: "r"(_m), "r"(_p) : "memory"); } \
} while (0)

#if TC_OK
#define BULK(d, s, mb) asm volatile( \
    "cp.async.bulk.shared::cta.global.mbarrier::complete_tx::bytes [%0], [%1], %2, [%3];" \
    :: "r"((uint32_t)(d)), "l"(s), "r"(8192u), "r"((uint32_t)(mb)) : "memory")
#define TC_ALLOC_CG2(sa, n)   asm volatile("tcgen05.alloc.cta_group::2.sync.aligned.shared::cta.b32 [%0], %1;" :: "r"((uint32_t)(sa)), "r"((uint32_t)(n)) : "memory")
#define TC_DEALLOC_CG2(tm, n) asm volatile("tcgen05.dealloc.cta_group::2.sync.aligned.b32 %0, %1;" :: "r"(tm), "r"((uint32_t)(n)))
#define TC_RELINQ_CG2()       asm volatile("tcgen05.relinquish_alloc_permit.cta_group::2.sync.aligned;")
#define TC_COMMIT_MC2(mb, mask) asm volatile( \
    "tcgen05.commit.cta_group::2.mbarrier::arrive::one.shared::cluster.multicast::cluster.b64 [%0], %1;" \
    :: "r"((uint32_t)(mb)), "h"((uint16_t)(mask)) : "memory")
#define TC_FENCE_AFTER()  asm volatile("tcgen05.fence::after_thread_sync;" ::: "memory")
#define TC_FENCE_BEFORE() asm volatile("tcgen05.fence::before_thread_sync;" ::: "memory")
#define TC_WAIT_LD()      asm volatile("tcgen05.wait::ld.sync.aligned;" ::: "memory")
#define TC_LD_X32(r, ta) \
    asm volatile("tcgen05.ld.sync.aligned.32x32b.x32.b32 " \
        "{%0,%1,%2,%3,%4,%5,%6,%7,%8,%9,%10,%11,%12,%13,%14,%15," \
        "%16,%17,%18,%19,%20,%21,%22,%23,%24,%25,%26,%27,%28,%29,%30,%31}, [%32];" \
        : "=r"((r)[0]), "=r"((r)[1]), "=r"((r)[2]), "=r"((r)[3]), "=r"((r)[4]), "=r"((r)[5]), "=r"((r)[6]), "=r"((r)[7]), \
          "=r"((r)[8]), "=r"((r)[9]), "=r"((r)[10]), "=r"((r)[11]), "=r"((r)[12]), "=r"((r)[13]), "=r"((r)[14]), "=r"((r)[15]), \
          "=r"((r)[16]), "=r"((r)[17]), "=r"((r)[18]), "=r"((r)[19]), "=r"((r)[20]), "=r"((r)[21]), "=r"((r)[22]), "=r"((r)[23]), \
          "=r"((r)[24]), "=r"((r)[25]), "=r"((r)[26]), "=r"((r)[27]), "=r"((r)[28]), "=r"((r)[29]), "=r"((r)[30]), "=r"((r)[31]) \
        : "r"(ta))

// SW64 K-major descriptor: layout=4, version=1, SBO=32, LBO=1
static constexpr uint64_t DESC_SW64 =
    (uint64_t(4) << 61) | (uint64_t(1) << 46) | (uint64_t(32) << 32) | (uint64_t(1) << 16);
#define MK_DESC(a) (DESC_SW64 | ((uint64_t)((a) >> 4) & 0x3FFF))
// idesc kind::f16 cg2: F32 out, BF16 a/b, M=256 (16<<24), N=256 (32<<17)
#define IDESC_CG2 ((1u << 4) | (1u << 7) | (1u << 10) | (32u << 17) | (16u << 24))

__device__ __forceinline__ void mma_cg2(uint32_t d, uint64_t a, uint64_t b, uint32_t en) {
    asm volatile("{\n\t.reg .pred p;\n\tsetp.ne.u32 p, %4, 0;\n\t"
        "tcgen05.mma.cta_group::2.kind::f16 [%0], %1, %2, %3, {%5,%5,%5,%5,%5,%5,%5,%5}, p;\n\t}"
        :: "r"(d), "l"(a), "l"(b), "r"(IDESC_CG2), "r"(en), "r"(0u) : "memory");
}
#endif  // TC_OK

__device__ __forceinline__ uint32_t pack_hi(float a, float b, uint32_t& lo) {
    __nv_bfloat16 h0 = __float2bfloat16(a), h1 = __float2bfloat16(b);
    __nv_bfloat16 l0 = __float2bfloat16(a - __bfloat162float(h0));
    __nv_bfloat16 l1 = __float2bfloat16(b - __bfloat162float(h1));
    lo = (uint32_t)__bfloat16_as_ushort(l0) | ((uint32_t)__bfloat16_as_ushort(l1) << 16);
    return (uint32_t)__bfloat16_as_ushort(h0) | ((uint32_t)__bfloat16_as_ushort(h1) << 16);
}

// ---------------- routing ----------------
__global__ void k_zero() { if (threadIdx.x < E) g_counts[threadIdx.x] = 0; }

__global__ void k_router(const float* __restrict__ x, const float* __restrict__ gate,
                         float* __restrict__ logits_out, int T) {
    __shared__ float sg[E * H];
    for (int i = threadIdx.x; i < E * H; i += blockDim.x) sg[i] = gate[i];
    __syncthreads();
    int warp = threadIdx.x >> 5, lane = threadIdx.x & 31;
    int t = blockIdx.x * 8 + warp;
    if (t >= T) return;
    const float* xr = x + (size_t)t * H;
    float acc[E];
#pragma unroll
    for (int e = 0; e < E; e++) acc[e] = 0.f;
    for (int k = lane; k < H; k += 32) {
        float xv = xr[k];
#pragma unroll
        for (int e = 0; e < E; e++) acc[e] += xv * sg[e * H + k];
    }
#pragma unroll
    for (int e = 0; e < E; e++)
#pragma unroll
        for (int o = 16; o > 0; o >>= 1) acc[e] += __shfl_down_sync(0xffffffffu, acc[e], o);
    if (lane == 0) {
#pragma unroll
        for (int e = 0; e < E; e++) logits_out[(size_t)t * E + e] = acc[e];
        int e0 = 0; float l0 = acc[0];
#pragma unroll
        for (int e = 1; e < E; e++) if (acc[e] > l0) { l0 = acc[e]; e0 = e; }
        int e1 = -1; float l1 = -1e30f;
#pragma unroll
        for (int e = 0; e < E; e++) if (e != e0 && acc[e] > l1) { l1 = acc[e]; e1 = e; }
        float s = 0.f, pe[E];
#pragma unroll
        for (int e = 0; e < E; e++) { pe[e] = expf(acc[e] - l0); s += pe[e]; }
        float p0 = pe[e0] / s, p1 = pe[e1] / s;
        float inv = 1.f / (p0 + p1);
        int q0 = atomicAdd(&g_counts[e0], 1);
        g_list[e0 * T_MAX + q0] = (t << 1);
        g_wts[(t << 1)] = p0 * inv;
        int q1 = atomicAdd(&g_counts[e1], 1);
        g_list[e1 * T_MAX + q1] = (t << 1) | 1;
        g_wts[(t << 1) | 1] = p1 * inv;
    }
}

__global__ void k_base() {
    if (threadIdx.x == 0) {
        int s = 0, ps = 0, j13 = 0, j2 = 0;
#pragma unroll
        for (int e = 0; e < E; e++) {
            g_base[e] = s;  g_pbase[e] = ps;
            g_jb13[e] = j13; g_jb2[e] = j2;
            int np = (g_counts[e] + 511) >> 9;
            j13 += np * (FF / 128);
            j2  += np * (H / 256);
            s += g_counts[e];
            ps += (g_counts[e] + 511) & ~511;
        }
        g_J13 = j13;  g_J2 = j2;
    }
}

// fp32 -> bf16 hi/lo, pre-tiled + pre-swizzled
__global__ void k_split8(const float* __restrict__ src, __nv_bfloat16* __restrict__ hi,
                         __nv_bfloat16* __restrict__ lo, long n8, int K, int nkc) {
    long i = (long)blockIdx.x * blockDim.x + threadIdx.x;
    if (i >= n8) return;
    long f = i * 8;
    int row = (int)(f / K), k0 = (int)(f % K);
    int kc = k0 >> 5, c = (k0 & 31) >> 3;
    int rr = row & 127, tr = row >> 7;
    size_t off = ((size_t)tr * nkc + kc) * TB + (size_t)rr * 64 + ((c ^ ((rr >> 1) & 3)) << 4);
    const float4* s4 = (const float4*)(src + f);
    float4 a = s4[0], b = s4[1];
    float v[8] = {a.x, a.y, a.z, a.w, b.x, b.y, b.z, b.w};
    uint32_t ph[4], pl[4];
#pragma unroll
    for (int j = 0; j < 4; j++) ph[j] = pack_hi(v[2 * j], v[2 * j + 1], pl[j]);
    *(uint4*)((char*)hi + off) = make_uint4(ph[0], ph[1], ph[2], ph[3]);
    *(uint4*)((char*)lo + off) = make_uint4(pl[0], pl[1], pl[2], pl[3]);
}

// gather x rows into expert-grouped (padded) tiled hi/lo
__global__ void k_gather(const float* __restrict__ x, int total) {
    int g = blockIdx.x;
    if (g >= total) return;
    int e = 0;
#pragma unroll
    for (int k = 1; k < E; k++) if (g >= g_base[k]) e = k;
    int pos = g - g_base[e];
    int tok = g_list[e * T_MAX + pos] >> 1;
    int prow = g_pbase[e] + pos;
    int rr = prow & 127, tr = prow >> 7;
    int tid = threadIdx.x;                 // 0..127
    int kc = tid >> 2, c = tid & 3;
    size_t off = ((size_t)tr * NKC_H + kc) * TB + (size_t)rr * 64 + ((c ^ ((rr >> 1) & 3)) << 4);
    const float4* src = (const float4*)(x + (size_t)tok * H + tid * 8);
    float4 a = src[0], b = src[1];
    float v[8] = {a.x, a.y, a.z, a.w, b.x, b.y, b.z, b.w};
    uint32_t ph[4], pl[4];
#pragma unroll
    for (int j = 0; j < 4; j++) ph[j] = pack_hi(v[2 * j], v[2 * j + 1], pl[j]);
    *(uint4*)((char*)g_ax_hi + off) = make_uint4(ph[0], ph[1], ph[2], ph[3]);
    *(uint4*)((char*)g_ax_lo + off) = make_uint4(pl[0], pl[1], pl[2], pl[3]);
}

#define SM_T 1024

#if TC_OK
// one stage fill (6 tiles, 48KB) -> local full barrier (expect must already be armed)
__device__ __forceinline__ void bulk6(uint32_t sb, int buf,
    const __nv_bfloat16* Ah, const __nv_bfloat16* Al, int trA, int nkcA,
    const __nv_bfloat16* Wh, const __nv_bfloat16* Wl, int trW, int nkcW, int kc) {
    uint32_t mb = sb + 8 + buf * 8;
    uint32_t dst = sb + SM_T + buf * 6 * TB;
    size_t a0 = ((size_t)trA * nkcA + kc) * TB;
    size_t a1 = ((size_t)(trA + 1) * nkcA + kc) * TB;
    size_t w  = ((size_t)trW * nkcW + kc) * TB;
    BULK(dst + 0 * TB, (const char*)Ah + a0, mb);
    BULK(dst + 1 * TB, (const char*)Al + a0, mb);
    BULK(dst + 2 * TB, (const char*)Ah + a1, mb);
    BULK(dst + 3 * TB, (const char*)Al + a1, mb);
    BULK(dst + 4 * TB, (const char*)Wh + w, mb);
    BULK(dst + 5 * TB, (const char*)Wl + w, mb);
}

// mainloop for one job (tid0 only). Expects chunks 0..2 already in flight.
// Parity formulas are per-job-relative; valid because NCH % 8 == 0 keeps
// every mbarrier's phase invariant across job boundaries.
__device__ void mainloop(uint32_t sb, uint32_t tm, int NCH, int rank,
    const __nv_bfloat16* Ah, const __nv_bfloat16* Al, int trA, int nkcA,
    const __nv_bfloat16* Wh, const __nv_bfloat16* Wl, int trW, int nkcW) {
    for (int i = 0; i < NCH; i++) {
        int b = i & (NST - 1);
        MBAR_WAIT(sb + 8 + b * 8, (i >> 2) & 1);
        MBAR_EXPECT(sb + 8 + b * 8, 6 * TB);          // re-arm for next use
        if (rank == 0) {
            uint32_t tb = sb + SM_T + b * 6 * TB;
            uint64_t dA0h = MK_DESC(tb),          dA0l = MK_DESC(tb + TB);
            uint64_t dA1h = MK_DESC(tb + 2 * TB), dA1l = MK_DESC(tb + 3 * TB);
            uint64_t dWh  = MK_DESC(tb + 4 * TB), dWl  = MK_DESC(tb + 5 * TB);
#pragma unroll
            for (int ks = 0; ks < 2; ks++) {
                uint64_t o = (uint64_t)(2 * ks);
                uint32_t en = (i > 0 || ks > 0) ? 1u : 0u;
                mma_cg2(tm,       dA0h + o, dWh + o, en);
                mma_cg2(tm,       dA0h + o, dWl + o, 1);
                mma_cg2(tm,       dA0l + o, dWh + o, 1);
                mma_cg2(tm + 256, dA1h + o, dWh + o, en);
                mma_cg2(tm + 256, dA1h + o, dWl + o, 1);
                mma_cg2(tm + 256, dA1l + o, dWh + o, 1);
            }
            TC_COMMIT_MC2(sb + 48 + b * 8, 0x3);
        } else {
            ARRIVE_REMOTE0(sb + 8 + b * 8);
        }
        if (i + 3 < NCH) {
            int nb = (i + 3) & (NST - 1);
            if (i >= 1) MBAR_WAIT(sb + 48 + nb * 8, ((i - 1) >> 2) & 1);
            bulk6(sb, nb, Ah, Al, trA, nkcA, Wh, Wl, trW, nkcW, i + 3);
        }
    }
    for (int c = NCH - NST; c < NCH; c++)
        MBAR_WAIT(sb + 48 + (c & (NST - 1)) * 8, (c >> 2) & 1);
}

__device__ __forceinline__ int job_e(const int* jb, int j) {
    int e = 0;
#pragma unroll
    for (int k = 1; k < E; k++) if (j >= jb[k]) e = k;
    return e;
}
#endif

// ---------------- persistent cg2 GEMM13: pair BM=512, BN=128 ----------------
__global__ __launch_bounds__(256, 1) __cluster_dims__(2, 1, 1) void k_mma13() {
#if TC_OK
    int rank = (int)cta_rank();
    int pair = blockIdx.x >> 1;
    int npair = gridDim.x >> 1;
    extern __shared__ char sm[];
    uint32_t sb = smem_u32(sm);
    int tid = threadIdx.x, wid = tid >> 5, lid = tid & 31;

    if (wid == 0) TC_ALLOC_CG2(sb, 512);
    if (tid == 0) {
#pragma unroll
        for (int b = 0; b < NST; b++) {
            MBAR_INIT(sb + 8 + b * 8, rank == 0 ? 2 : 1);
            MBAR_INIT(sb + 48 + b * 8, 1);
            MBAR_EXPECT(sb + 8 + b * 8, 6 * TB);
        }
    }
    __syncthreads();
    CLUSTER_SYNC();
    uint32_t tm;
    asm volatile("ld.shared.b32 %0, [%1];" : "=r"(tm) : "r"(sb));

    int J = g_J13;
    // prefill first job
    if (tid == 0 && pair < J) {
        int e = job_e(g_jb13, pair);
        int local = pair - g_jb13[e];
        int trA = (g_pbase[e] + (local >> 5) * 512 + rank * 256) >> 7;
        int trW = (e * FF + (local & 31) * 128) >> 7;
        const __nv_bfloat16* Wh = rank ? g_w3h : g_w1h;
        const __nv_bfloat16* Wl = rank ? g_w3l : g_w1l;
        bulk6(sb, 0, g_ax_hi, g_ax_lo, trA, NKC_H, Wh, Wl, trW, NKC_H, 0);
        bulk6(sb, 1, g_ax_hi, g_ax_lo, trA, NKC_H, Wh, Wl, trW, NKC_H, 1);
        bulk6(sb, 2, g_ax_hi, g_ax_lo, trA, NKC_H, Wh, Wl, trW, NKC_H, 2);
    }

    for (int j = pair; j < J; j += npair) {
        int e = job_e(g_jb13, j);
        int local = j - g_jb13[e];
        int cnt = g_counts[e];
        int row0 = (local >> 5) * 512;
        int n0 = (local & 31) * 128;
        int rbase = g_pbase[e] + row0 + rank * 256;

        if (tid == 0) {
            const __nv_bfloat16* Wh = rank ? g_w3h : g_w1h;
            const __nv_bfloat16* Wl = rank ? g_w3l : g_w1l;
            mainloop(sb, tm, NKC_H, rank, g_ax_hi, g_ax_lo, rbase >> 7, NKC_H,
                     Wh, Wl, (e * FF + n0) >> 7, NKC_H);
            int jn = j + npair;
            if (jn < J) {   // prefill next job; overlaps epilogue (SMEM only)
                int en_ = job_e(g_jb13, jn);
                int ln = jn - g_jb13[en_];
                int trA = (g_pbase[en_] + (ln >> 5) * 512 + rank * 256) >> 7;
                int trW = (en_ * FF + (ln & 31) * 128) >> 7;
                bulk6(sb, 0, g_ax_hi, g_ax_lo, trA, NKC_H, Wh, Wl, trW, NKC_H, 0);
                bulk6(sb, 1, g_ax_hi, g_ax_lo, trA, NKC_H, Wh, Wl, trW, NKC_H, 1);
                bulk6(sb, 2, g_ax_hi, g_ax_lo, trA, NKC_H, Wh, Wl, trW, NKC_H, 2);
            }
        }
        __syncthreads();
        TC_FENCE_AFTER();

        int a = wid >> 2, sub = wid & 3;
        int lrow = a * 128 + sub * 32 + lid;
        bool valid = (row0 + rank * 256 + lrow) < cnt;
        int prow = rbase + lrow;
        int rr = prow & 127, tr = prow >> 7, sw = (rr >> 1) & 3;
#pragma unroll
        for (int c0 = 0; c0 < 128; c0 += 32) {
            uint32_t d1[32], d3[32];
            TC_LD_X32(d1, tm + a * 256 + c0);
            TC_LD_X32(d3, tm + a * 256 + 128 + c0);
            TC_WAIT_LD();
            if (valid) {
                uint32_t ph[16], pl[16];
#pragma unroll
                for (int jq = 0; jq < 16; jq++) {
                    float h0 = __uint_as_float(d1[2 * jq]),     v0 = __uint_as_float(d3[2 * jq]);
                    float h1 = __uint_as_float(d1[2 * jq + 1]), v1 = __uint_as_float(d3[2 * jq + 1]);
                    float a0 = (h0 / (1.f + __expf(-h0))) * v0;
                    float a1 = (h1 / (1.f + __expf(-h1))) * v1;
                    ph[jq] = pack_hi(a0, a1, pl[jq]);
                }
                int kc = (n0 >> 5) + (c0 >> 5);
                size_t tbo = ((size_t)tr * NKC_F + kc) * TB + (size_t)rr * 64;
#pragma unroll
                for (int q = 0; q < 4; q++) {
                    size_t o = tbo + ((q ^ sw) << 4);
                    *(uint4*)((char*)g_act_hi + o) = make_uint4(ph[4 * q], ph[4 * q + 1], ph[4 * q + 2], ph[4 * q + 3]);
                    *(uint4*)((char*)g_act_lo + o) = make_uint4(pl[4 * q], pl[4 * q + 1], pl[4 * q + 2], pl[4 * q + 3]);
                }
            }
        }
        TC_FENCE_BEFORE();
        __syncthreads();
    }
    if (wid == 0) { TC_RELINQ_CG2(); TC_DEALLOC_CG2(tm, 512); }
    CLUSTER_SYNC();
#endif
}

// ---------------- persistent cg2 GEMM2: pair BM=512, BN=256 ----------------
__global__ __launch_bounds__(256, 1) __cluster_dims__(2, 1, 1) void k_mma2() {
#if TC_OK
    int rank = (int)cta_rank();
    int pair = blockIdx.x >> 1;
    int npair = gridDim.x >> 1;
    extern __shared__ char sm[];
    uint32_t sb = smem_u32(sm);
    int tid = threadIdx.x, wid = tid >> 5, lid = tid & 31;

    if (wid == 0) TC_ALLOC_CG2(sb, 512);
    if (tid == 0) {
#pragma unroll
        for (int b = 0; b < NST; b++) {
            MBAR_INIT(sb + 8 + b * 8, rank == 0 ? 2 : 1);
            MBAR_INIT(sb + 48 + b * 8, 1);
            MBAR_EXPECT(sb + 8 + b * 8, 6 * TB);
        }
    }
    __syncthreads();
    CLUSTER_SYNC();
    uint32_t tm;
    asm volatile("ld.shared.b32 %0, [%1];" : "=r"(tm) : "r"(sb));

    int J = g_J2;
    if (tid == 0 && pair < J) {
        int e = job_e(g_jb2, pair);
        int local = pair - g_jb2[e];
        int trA = (g_pbase[e] + (local >> 2) * 512 + rank * 256) >> 7;
        int trW = (e * H + (local & 3) * 256 + rank * 128) >> 7;
        bulk6(sb, 0, g_act_hi, g_act_lo, trA, NKC_F, g_w2h, g_w2l, trW, NKC_F, 0);
        bulk6(sb, 1, g_act_hi, g_act_lo, trA, NKC_F, g_w2h, g_w2l, trW, NKC_F, 1);
        bulk6(sb, 2, g_act_hi, g_act_lo, trA, NKC_F, g_w2h, g_w2l, trW, NKC_F, 2);
    }

    for (int j = pair; j < J; j += npair) {
        int e = job_e(g_jb2, j);
        int local = j - g_jb2[e];
        int cnt = g_counts[e];
        int row0 = (local >> 2) * 512;
        int n0 = (local & 3) * 256;
        int rbase = g_pbase[e] + row0 + rank * 256;

        if (tid == 0) {
            mainloop(sb, tm, NKC_F, rank, g_act_hi, g_act_lo, rbase >> 7, NKC_F,
                     g_w2h, g_w2l, (e * H + n0 + rank * 128) >> 7, NKC_F);
            int jn = j + npair;
            if (jn < J) {
                int en_ = job_e(g_jb2, jn);
                int ln = jn - g_jb2[en_];
                int trA = (g_pbase[en_] + (ln >> 2) * 512 + rank * 256) >> 7;
                int trW = (en_ * H + (ln & 3) * 256 + rank * 128) >> 7;
                bulk6(sb, 0, g_act_hi, g_act_lo, trA, NKC_F, g_w2h, g_w2l, trW, NKC_F, 0);
                bulk6(sb, 1, g_act_hi, g_act_lo, trA, NKC_F, g_w2h, g_w2l, trW, NKC_F, 1);
                bulk6(sb, 2, g_act_hi, g_act_lo, trA, NKC_F, g_w2h, g_w2l, trW, NKC_F, 2);
            }
        }
        __syncthreads();
        TC_FENCE_AFTER();

        int a = wid >> 2, sub = wid & 3;
        int lrow = a * 128 + sub * 32 + lid;
        bool valid = (row0 + rank * 256 + lrow) < cnt;
        int ts = 0; float w = 0.f;
        if (valid) { ts = g_list[e * T_MAX + row0 + rank * 256 + lrow]; w = g_wts[ts]; }
        float* yrow = g_ybuf + (size_t)ts * H + n0;
#pragma unroll
        for (int c0 = 0; c0 < 256; c0 += 32) {
            uint32_t d[32];
            TC_LD_X32(d, tm + a * 256 + c0);
            TC_WAIT_LD();
            if (valid) {
                float4* dst = (float4*)(yrow + c0);
#pragma unroll
                for (int q = 0; q < 8; q++)
                    dst[q] = make_float4(w * __uint_as_float(d[4 * q]), w * __uint_as_float(d[4 * q + 1]),
                                         w * __uint_as_float(d[4 * q + 2]), w * __uint_as_float(d[4 * q + 3]));
            }
        }
        TC_FENCE_BEFORE();
        __syncthreads();
    }
    if (wid == 0) { TC_RELINQ_CG2(); TC_DEALLOC_CG2(tm, 512); }
    CLUSTER_SYNC();
#endif
}

__global__ void k_combine(float* __restrict__ out, int T) {
    int i = blockIdx.x * blockDim.x + threadIdx.x;
    int total = T * (H / 4);
    if (i >= total) return;
    int t = i / (H / 4);
    int h4 = i - t * (H / 4);
    const float4* yb = (const float4*)g_ybuf;
    float4 a = yb[(size_t)(2 * t) * (H / 4) + h4];
    float4 b = yb[(size_t)(2 * t + 1) * (H / 4) + h4];
    ((float4*)out)[i] = make_float4(a.x + b.x, a.y + b.y, a.z + b.z, a.w + b.w);
}

// ---------------- launch ----------------
extern "C" void kernel_launch(void* const* d_in, const int* in_sizes, int n_in,
                              void* d_out, int out_size) {
    const float* x;
    const float* gate;
    if (in_sizes[0] > in_sizes[1]) { x = (const float*)d_in[0]; gate = (const float*)d_in[1]; }
    else                           { gate = (const float*)d_in[0]; x = (const float*)d_in[1]; }
    const float* w1 = (const float*)d_in[2];
    const float* w2 = (const float*)d_in[3];
    const float* w3 = (const float*)d_in[4];
    int T = (in_sizes[0] > in_sizes[1] ? in_sizes[0] : in_sizes[1]) / H;

    float* out = (float*)d_out;
    float* logits_out = out + (size_t)T * H;

    int smem = SM_T + NST * 6 * TB;  // 197,632
    cudaFuncSetAttribute(k_mma13, cudaFuncAttributeMaxDynamicSharedMemorySize, smem);
    cudaFuncSetAttribute(k_mma2,  cudaFuncAttributeMaxDynamicSharedMemorySize, smem);

    __nv_bfloat16 *w1h, *w1l, *w3h, *w3l, *w2h, *w2l;
    cudaGetSymbolAddress((void**)&w1h, g_w1h); cudaGetSymbolAddress((void**)&w1l, g_w1l);
    cudaGetSymbolAddress((void**)&w3h, g_w3h); cudaGetSymbolAddress((void**)&w3l, g_w3l);
    cudaGetSymbolAddress((void**)&w2h, g_w2h); cudaGetSymbolAddress((void**)&w2l, g_w2l);

    k_zero<<<1, 32>>>();
    k_router<<<(T + 7) / 8, 256>>>(x, gate, logits_out, T);
    k_base<<<1, 1>>>();

    long n8 = (long)E * FF * H / 8;
    int sblk = (int)((n8 + 255) / 256);
    k_split8<<<sblk, 256>>>(w1, w1h, w1l, n8, H, NKC_H);
    k_split8<<<sblk, 256>>>(w3, w3h, w3l, n8, H, NKC_H);
    k_split8<<<sblk, 256>>>(w2, w2h, w2l, n8, FF, NKC_F);
    k_gather<<<2 * T, 128>>>(x, 2 * T);

    // persistent cg2 launches: 148 CTAs = 74 pairs, cluster (2,1,1)
    cudaLaunchAttribute attrs[1];
    attrs[0].id = cudaLaunchAttributeClusterDimension;
    attrs[0].val.clusterDim.x = 2; attrs[0].val.clusterDim.y = 1; attrs[0].val.clusterDim.z = 1;

    cudaLaunchConfig_t cfg13 = {};
    cfg13.gridDim  = dim3(NCTA, 1, 1);
    cfg13.blockDim = dim3(256, 1, 1);
    cfg13.dynamicSmemBytes = smem;
    cfg13.attrs = attrs; cfg13.numAttrs = 1;
    cudaLaunchKernelEx(&cfg13, k_mma13);

    cudaLaunchConfig_t cfg2 = {};
    cfg2.gridDim  = dim3(NCTA, 1, 1);
    cfg2.blockDim = dim3(256, 1, 1);
    cfg2.dynamicSmemBytes = smem;
    cfg2.attrs = attrs; cfg2.numAttrs = 1;
    cudaLaunchKernelEx(&cfg2, k_mma2);

    k_combine<<<(T * (H / 4) + 255) / 256, 256>>>(out, T);
}